// round 13
// baseline (speedup 1.0000x reference)
#include <cuda_runtime.h>
#include <cuda_fp16.h>
#include <cuda_bf16.h>

#define NMAX 100000
#define EMAX 1200000
#define CSRMAX (NMAX + EMAX)

// ---------------- scratch (device globals; no allocations allowed) ----------
__device__ float   g_h0[NMAX * 64];     // proj output / residual
__device__ float   g_h1[NMAX * 64];     // layer1 output (residual for layer2)
__device__ __half2 g_tmpA[NMAX * 32];   // dinv-scaled fp16 table (buffer A)
__device__ __half2 g_tmpB[NMAX * 32];   // dinv-scaled fp16 table (buffer B)
__device__ float   g_byp[NMAX * 3];     // bypass projection
__device__ float   g_dinv[NMAX];
__device__ int     g_deg[NMAX];         // zero at start of every execution (fill re-zeroes)
__device__ int     g_rowptr[NMAX + 1];
__device__ int     g_cursor[NMAX];
__device__ int     g_csr[CSRMAX];       // src index only (tables pre-scaled by dinv[src])
__device__ int     g_bsum[256];

// ---------------- f32x2 helpers -----------------------------------------------
__device__ __forceinline__ void ffma2(unsigned long long& d,
                                      unsigned long long a,
                                      unsigned long long b) {
    asm("fma.rn.f32x2 %0, %1, %2, %0;" : "+l"(d) : "l"(a), "l"(b));
}
__device__ __forceinline__ unsigned long long dup2(float x) {
    unsigned long long r;
    unsigned u = __float_as_uint(x);
    asm("mov.b64 %0, {%1, %1};" : "=l"(r) : "r"(u));
    return r;
}
__device__ __forceinline__ float lo32(unsigned long long v) {
    return __uint_as_float((unsigned)(v & 0xffffffffull));
}
__device__ __forceinline__ float hi32(unsigned long long v) {
    return __uint_as_float((unsigned)(v >> 32));
}

// ---------------- merged1: proj GEMM (+bypass) INTERLEAVED with hist --------
__global__ void __launch_bounds__(128) merged1_kernel(
    const float* __restrict__ x, const float* __restrict__ Wp,
    const float* __restrict__ bp, const float* __restrict__ Wb,
    const float* __restrict__ bb, float* __restrict__ h0,
    float* __restrict__ byp, int N,
    const int* __restrict__ col, int* __restrict__ deg, int E, int HB)
{
    __shared__ float Xs[64][65];
    __shared__ float Ws[64][66];
    __shared__ float Bs[3][65];
    int tid = threadIdx.x;
    int bid = blockIdx.x;

    int gemm_id;
    if (bid < 2 * HB) {
        if (bid & 1) {
            int base = (bid >> 1) * 1024;
#pragma unroll
            for (int j = 0; j < 8; ++j) {
                int e = base + j * 128 + tid;
                if (e < E) atomicAdd(&deg[col[e]], 1);
            }
            return;
        }
        gemm_id = bid >> 1;
    } else {
        gemm_id = HB + (bid - 2 * HB);
    }

    int row0 = gemm_id * 64;
    int tr  = tid >> 3;
    int tc2 = (tid & 7) * 2;

    unsigned long long acc[4][4];
    float bacc[4] = {0.f, 0.f, 0.f, 0.f};
#pragma unroll
    for (int i = 0; i < 4; ++i)
#pragma unroll
        for (int j = 0; j < 4; ++j) acc[i][j] = 0ull;

    for (int kc = 0; kc < 2; ++kc) {
        int kbase = kc * 64;
        for (int l = tid; l < 1024; l += 128) {
            int r = l >> 4, k4 = (l & 15) * 4;
            int n = row0 + r;
            float4 xv = make_float4(0.f, 0.f, 0.f, 0.f);
            if (n < N) xv = *(const float4*)(x + n * 128 + kbase + k4);
            Xs[r][k4] = xv.x; Xs[r][k4 + 1] = xv.y; Xs[r][k4 + 2] = xv.z; Xs[r][k4 + 3] = xv.w;
            float4 wv = *(const float4*)(Wp + r * 128 + kbase + k4);
            Ws[k4][r] = wv.x; Ws[k4 + 1][r] = wv.y; Ws[k4 + 2][r] = wv.z; Ws[k4 + 3][r] = wv.w;
        }
        for (int l = tid; l < 192; l += 128)
            Bs[l >> 6][l & 63] = Wb[(l >> 6) * 128 + kbase + (l & 63)];
        __syncthreads();

        int tc = tid & 7;
#pragma unroll 4
        for (int k = 0; k < 64; ++k) {
            float a_s[4];
            unsigned long long aa[4], wv[4];
#pragma unroll
            for (int i = 0; i < 4; ++i) { a_s[i] = Xs[tr + i * 16][k]; aa[i] = dup2(a_s[i]); }
#pragma unroll
            for (int j = 0; j < 4; ++j)
                wv[j] = *(const unsigned long long*)&Ws[k][tc2 + 16 * j];
#pragma unroll
            for (int i = 0; i < 4; ++i)
#pragma unroll
                for (int j = 0; j < 4; ++j) ffma2(acc[i][j], aa[i], wv[j]);
            if (tc < 3) {
                float bw = Bs[tc][k];
#pragma unroll
                for (int i = 0; i < 4; ++i) bacc[i] = fmaf(a_s[i], bw, bacc[i]);
            }
        }
        __syncthreads();
    }

    int tc = tid & 7;
#pragma unroll
    for (int i = 0; i < 4; ++i) {
        int n = row0 + tr + i * 16;
        if (n < N) {
#pragma unroll
            for (int j = 0; j < 4; ++j) {
                int c = tc2 + 16 * j;
                float2 v;
                v.x = lo32(acc[i][j]) + bp[c];
                v.y = hi32(acc[i][j]) + bp[c + 1];
                *(float2*)(h0 + n * 64 + c) = v;
            }
            if (tc < 3) byp[n * 3 + tc] = bacc[i] + bb[tc];
        }
    }
}

// ---------------- scan1: block prefix of (deg+1), block sums, AND dinv ------
__global__ void __launch_bounds__(128) scan1_kernel(
    const int* __restrict__ deg, int* __restrict__ rowptr,
    int* __restrict__ bsum, float* __restrict__ dinv, int N)
{
    __shared__ int sc[128];
    int tid = threadIdx.x;
    int sb = blockIdx.x;
    int i0 = sb * 1024 + tid * 8;
    int dl[8];
    int s = 0;
#pragma unroll
    for (int j = 0; j < 8; ++j) {
        int i = i0 + j;
        int dd = 0;
        if (i < N) {
            dd = deg[i] + 1;
            dinv[i] = rsqrtf((float)dd);
        }
        dl[j] = s;
        s += dd;
    }
    sc[tid] = s;
    __syncthreads();
    for (int off = 1; off < 128; off <<= 1) {
        int u = (tid >= off) ? sc[tid - off] : 0;
        __syncthreads();
        sc[tid] += u;
        __syncthreads();
    }
    int excl = tid ? sc[tid - 1] : 0;
#pragma unroll
    for (int j = 0; j < 8; ++j) {
        int i = i0 + j;
        if (i < N) rowptr[i] = excl + dl[j];
    }
    if (tid == 127) bsum[sb] = sc[127];
}

// ---------------- merged2: conv1 GEMM (dinv-scaled) INTERLEAVED w/ scan3 ----
__global__ void __launch_bounds__(128) merged2_kernel(
    const float* __restrict__ A, const float* __restrict__ W,
    const float* __restrict__ dinv, __half2* __restrict__ out, int N,
    const int* __restrict__ deg, int* __restrict__ rowptr,
    const int* __restrict__ bsum, int* __restrict__ cursor,
    int* __restrict__ csr, int nb, int SB3)
{
    __shared__ float Xs[64][65];
    __shared__ float Ws[64][66];
    int tid = threadIdx.x;
    int bid = blockIdx.x;

    int gemm_id;
    if (bid < 2 * SB3) {
        if (bid & 1) {
            __shared__ int sm3[128];
            int s3 = bid >> 1;
            sm3[tid] = (tid < nb) ? bsum[tid] : 0;
            __syncthreads();
            for (int off = 1; off < 128; off <<= 1) {
                int u = (tid >= off) ? sm3[tid - off] : 0;
                __syncthreads();
                sm3[tid] += u;
                __syncthreads();
            }
            int myb = s3 >> 1;
            int pref = myb ? sm3[myb - 1] : 0;
#pragma unroll
            for (int j = 0; j < 4; ++j) {
                int i = s3 * 512 + j * 128 + tid;
                if (i < N) {
                    int rp = rowptr[i] + pref;
                    rowptr[i] = rp;
                    cursor[i] = rp + 1;
                    csr[rp] = i;
                    if (i == N - 1) rowptr[N] = rp + deg[i] + 1;
                }
            }
            return;
        }
        gemm_id = bid >> 1;
    } else {
        gemm_id = SB3 + (bid - 2 * SB3);
    }

    int row0 = gemm_id * 64;
    int tr  = tid >> 3;
    int tc2 = (tid & 7) * 2;

    for (int l = tid; l < 1024; l += 128) {
        int r = l >> 4, k4 = (l & 15) * 4;
        int n = row0 + r;
        float4 xv = make_float4(0.f, 0.f, 0.f, 0.f);
        if (n < N) xv = *(const float4*)(A + n * 64 + k4);
        Xs[r][k4] = xv.x; Xs[r][k4 + 1] = xv.y; Xs[r][k4 + 2] = xv.z; Xs[r][k4 + 3] = xv.w;
        float4 wv = *(const float4*)(W + r * 64 + k4);
        Ws[k4][r] = wv.x; Ws[k4 + 1][r] = wv.y; Ws[k4 + 2][r] = wv.z; Ws[k4 + 3][r] = wv.w;
    }
    __syncthreads();

    unsigned long long acc[4][4];
#pragma unroll
    for (int i = 0; i < 4; ++i)
#pragma unroll
        for (int j = 0; j < 4; ++j) acc[i][j] = 0ull;

#pragma unroll 4
    for (int k = 0; k < 64; ++k) {
        unsigned long long aa[4], wv[4];
#pragma unroll
        for (int i = 0; i < 4; ++i) aa[i] = dup2(Xs[tr + i * 16][k]);
#pragma unroll
        for (int j = 0; j < 4; ++j)
            wv[j] = *(const unsigned long long*)&Ws[k][tc2 + 16 * j];
#pragma unroll
        for (int i = 0; i < 4; ++i)
#pragma unroll
            for (int j = 0; j < 4; ++j) ffma2(acc[i][j], aa[i], wv[j]);
    }

#pragma unroll
    for (int i = 0; i < 4; ++i) {
        int n = row0 + tr + i * 16;
        if (n < N) {
            float dvn = dinv[n];
#pragma unroll
            for (int j = 0; j < 4; ++j) {
                float2 v = make_float2(lo32(acc[i][j]) * dvn, hi32(acc[i][j]) * dvn);
                out[n * 32 + (tc2 >> 1) + 8 * j] = __float22half2_rn(v);
            }
        }
    }
}

// ---------------- fill: 4 edges per thread (MLP), + deg reset ---------------
__global__ void __launch_bounds__(256) fill_kernel(
    const int* __restrict__ row, const int* __restrict__ col,
    int* __restrict__ cursor, int* __restrict__ csr,
    int* __restrict__ deg, int E, int N)
{
    int base = blockIdx.x * 1024 + threadIdx.x;
    int c4[4], r4[4];
#pragma unroll
    for (int j = 0; j < 4; ++j) {
        int e = base + j * 256;
        if (e < N) deg[e] = 0;           // reset for next execution
        c4[j] = (e < E) ? col[e] : -1;
        r4[j] = (e < E) ? row[e] : 0;
    }
    int pos[4];
#pragma unroll
    for (int j = 0; j < 4; ++j)
        pos[j] = (c4[j] >= 0) ? atomicAdd(&cursor[c4[j]], 1) : 0;
#pragma unroll
    for (int j = 0; j < 4; ++j)
        if (c4[j] >= 0) csr[pos[j]] = r4[j];
}

// ---------------- fused: agg layer (mode 0) + next-layer GEMM ---------------
// tmp_in and tmp_out are DISTINCT buffers (double-buffered; R12 aliased them
// and raced). 256 threads, 128 nodes per block.
__global__ void __launch_bounds__(256) agg_gemm_kernel(
    const __half2* __restrict__ tmp_in, const int* __restrict__ csr,
    const int* __restrict__ rowptr, const float* __restrict__ dinv,
    const float* __restrict__ convb, const float* __restrict__ bng,
    const float* __restrict__ bnb, const float* __restrict__ resid,
    float* __restrict__ h_out, const float* __restrict__ W,
    __half2* __restrict__ tmp_out, int N)
{
    __shared__ float Xs[128][68];
    __shared__ float Ws[64][66];
    int tid = threadIdx.x;
    int wid = tid >> 5, lane = tid & 31;
    int half = lane >> 4, sub = lane & 15;
    int row0 = blockIdx.x * 128;

    // weight tile (transposed): Ws[k][c] = W[c][k]
    for (int l = tid; l < 1024; l += 256) {
        int r = l >> 4, k4 = (l & 15) * 4;
        float4 wv = *(const float4*)(W + r * 64 + k4);
        Ws[k4][r] = wv.x; Ws[k4 + 1][r] = wv.y; Ws[k4 + 2][r] = wv.z; Ws[k4 + 3][r] = wv.w;
    }

    const float bninv = rsqrtf(1.0f + 1e-5f);
    int c = sub * 4;
    float4 cb = *(const float4*)(convb + c);
    float4 bg = *(const float4*)(bng + c);
    float4 bo = *(const float4*)(bnb + c);

    const uint2* hp = (const uint2*)tmp_in;
    for (int i = 0; i < 16; ++i) {
        int v = row0 + wid * 16 + i;
        float a0 = 0.f, a1 = 0.f, a2 = 0.f, a3 = 0.f;
        if (v < N) {
            int s = rowptr[v];
            int e = rowptr[v + 1];
            int p = s + half;
            for (; p + 2 < e; p += 4) {
                int s0 = csr[p];
                int s1 = csr[p + 2];
                uint2 r0 = hp[s0 * 16 + sub];
                uint2 r1 = hp[s1 * 16 + sub];
                float2 f00 = __half22float2(*(__half2*)&r0.x);
                float2 f01 = __half22float2(*(__half2*)&r0.y);
                float2 f10 = __half22float2(*(__half2*)&r1.x);
                float2 f11 = __half22float2(*(__half2*)&r1.y);
                a0 += f00.x + f10.x;
                a1 += f00.y + f10.y;
                a2 += f01.x + f11.x;
                a3 += f01.y + f11.y;
            }
            if (p < e) {
                int s0 = csr[p];
                uint2 r0 = hp[s0 * 16 + sub];
                float2 f00 = __half22float2(*(__half2*)&r0.x);
                float2 f01 = __half22float2(*(__half2*)&r0.y);
                a0 += f00.x;
                a1 += f00.y;
                a2 += f01.x;
                a3 += f01.y;
            }
        }
        a0 += __shfl_xor_sync(0xffffffffu, a0, 16);
        a1 += __shfl_xor_sync(0xffffffffu, a1, 16);
        a2 += __shfl_xor_sync(0xffffffffu, a2, 16);
        a3 += __shfl_xor_sync(0xffffffffu, a3, 16);

        if (half == 0) {
            int lr = wid * 16 + i;
            if (v < N) {
                float dv = dinv[v];
                float4 r = *(const float4*)(resid + v * 64 + c);
                float4 o;
                o.x = fmaxf(fmaf(fmaf(a0, dv, cb.x), bg.x * bninv, bo.x), 0.f) + r.x;
                o.y = fmaxf(fmaf(fmaf(a1, dv, cb.y), bg.y * bninv, bo.y), 0.f) + r.y;
                o.z = fmaxf(fmaf(fmaf(a2, dv, cb.z), bg.z * bninv, bo.z), 0.f) + r.z;
                o.w = fmaxf(fmaf(fmaf(a3, dv, cb.w), bg.w * bninv, bo.w), 0.f) + r.w;
                *(float4*)&Xs[lr][c] = o;
                if (h_out) *(float4*)(h_out + v * 64 + c) = o;
            } else {
                *(float4*)&Xs[lr][c] = make_float4(0.f, 0.f, 0.f, 0.f);
            }
        }
    }
    __syncthreads();

    // ---- GEMM from smem: 128 rows x 64 cols, K=64 ----
    int tr  = tid >> 3;            // 0..31
    int tc2 = (tid & 7) * 2;

    unsigned long long acc[4][4];
#pragma unroll
    for (int i = 0; i < 4; ++i)
#pragma unroll
        for (int j = 0; j < 4; ++j) acc[i][j] = 0ull;

#pragma unroll 4
    for (int k = 0; k < 64; ++k) {
        unsigned long long aa[4], wv[4];
#pragma unroll
        for (int i = 0; i < 4; ++i) aa[i] = dup2(Xs[tr + i * 32][k]);
#pragma unroll
        for (int j = 0; j < 4; ++j)
            wv[j] = *(const unsigned long long*)&Ws[k][tc2 + 16 * j];
#pragma unroll
        for (int i = 0; i < 4; ++i)
#pragma unroll
            for (int j = 0; j < 4; ++j) ffma2(acc[i][j], aa[i], wv[j]);
    }

#pragma unroll
    for (int i = 0; i < 4; ++i) {
        int n = row0 + tr + i * 32;
        if (n < N) {
            float dvn = dinv[n];
#pragma unroll
            for (int j = 0; j < 4; ++j) {
                float2 v = make_float2(lo32(acc[i][j]) * dvn, hi32(acc[i][j]) * dvn);
                tmp_out[n * 32 + (tc2 >> 1) + 8 * j] = __float22half2_rn(v);
            }
        }
    }
}

// ---------------- final aggregation (head fused) ----------------------------
__global__ void __launch_bounds__(256) agg_head_kernel(
    const __half2* __restrict__ tmp, const int* __restrict__ csr,
    const int* __restrict__ rowptr, const float* __restrict__ dinv,
    const float* __restrict__ convb, const float* __restrict__ bng,
    const float* __restrict__ bnb, const float* __restrict__ headW,
    const float* __restrict__ headb, const float* __restrict__ byp,
    float* __restrict__ out, int N)
{
    int gt = blockIdx.x * blockDim.x + threadIdx.x;
    int v = gt >> 5;
    int lane = gt & 31;
    if (v >= N) return;
    int half = lane >> 4;
    int sub  = lane & 15;

    const uint2* hp = (const uint2*)tmp;
    int s = rowptr[v];
    int e = rowptr[v + 1];

    float a0 = 0.f, a1 = 0.f, a2 = 0.f, a3 = 0.f;
    int p = s + half;
    for (; p + 2 < e; p += 4) {
        int s0 = csr[p];
        int s1 = csr[p + 2];
        uint2 r0 = hp[s0 * 16 + sub];
        uint2 r1 = hp[s1 * 16 + sub];
        float2 f00 = __half22float2(*(__half2*)&r0.x);
        float2 f01 = __half22float2(*(__half2*)&r0.y);
        float2 f10 = __half22float2(*(__half2*)&r1.x);
        float2 f11 = __half22float2(*(__half2*)&r1.y);
        a0 += f00.x + f10.x;
        a1 += f00.y + f10.y;
        a2 += f01.x + f11.x;
        a3 += f01.y + f11.y;
    }
    if (p < e) {
        int s0 = csr[p];
        uint2 r0 = hp[s0 * 16 + sub];
        float2 f00 = __half22float2(*(__half2*)&r0.x);
        float2 f01 = __half22float2(*(__half2*)&r0.y);
        a0 += f00.x;
        a1 += f00.y;
        a2 += f01.x;
        a3 += f01.y;
    }
    a0 += __shfl_xor_sync(0xffffffffu, a0, 16);
    a1 += __shfl_xor_sync(0xffffffffu, a1, 16);
    a2 += __shfl_xor_sync(0xffffffffu, a2, 16);
    a3 += __shfl_xor_sync(0xffffffffu, a3, 16);

    float dv = dinv[v];
    const float bninv = rsqrtf(1.0f + 1e-5f);

    float p0 = 0.f, p1 = 0.f, p2 = 0.f;
    if (half == 0) {
        int c = sub * 4;
        float4 cb = *(const float4*)(convb + c);
        float4 bg = *(const float4*)(bng + c);
        float4 bo = *(const float4*)(bnb + c);
        float v0 = fmaxf(fmaf(fmaf(a0, dv, cb.x), bg.x * bninv, bo.x), 0.f);
        float v1 = fmaxf(fmaf(fmaf(a1, dv, cb.y), bg.y * bninv, bo.y), 0.f);
        float v2 = fmaxf(fmaf(fmaf(a2, dv, cb.z), bg.z * bninv, bo.z), 0.f);
        float v3 = fmaxf(fmaf(fmaf(a3, dv, cb.w), bg.w * bninv, bo.w), 0.f);
        p0 = v0 * headW[c]       + v1 * headW[c + 1]       + v2 * headW[c + 2]       + v3 * headW[c + 3];
        p1 = v0 * headW[67 + c]  + v1 * headW[67 + c + 1]  + v2 * headW[67 + c + 2]  + v3 * headW[67 + c + 3];
        p2 = v0 * headW[134 + c] + v1 * headW[134 + c + 1] + v2 * headW[134 + c + 2] + v3 * headW[134 + c + 3];
    }
#pragma unroll
    for (int o = 8; o > 0; o >>= 1) {
        p0 += __shfl_xor_sync(0xffffffffu, p0, o);
        p1 += __shfl_xor_sync(0xffffffffu, p1, o);
        p2 += __shfl_xor_sync(0xffffffffu, p2, o);
    }
    if (lane == 0) {
        float b0 = byp[v * 3], b1 = byp[v * 3 + 1], b2 = byp[v * 3 + 2];
        p0 += headW[64] * b0 + headW[65] * b1 + headW[66] * b2 + headb[0];
        p1 += headW[67 + 64] * b0 + headW[67 + 65] * b1 + headW[67 + 66] * b2 + headb[1];
        p2 += headW[134 + 64] * b0 + headW[134 + 65] * b1 + headW[134 + 66] * b2 + headb[2];
        float kappa = fminf(fmaxf(p0 * 5.f + 2.5f, 0.2f), 10.f);
        float tau   = fminf(fmaxf(p2 + 0.5f, 0.05f), 2.f);
        out[v * 3]     = kappa;
        out[v * 3 + 1] = p1;
        out[v * 3 + 2] = tau;
    }
}

// ---------------- launch -----------------------------------------------------
extern "C" void kernel_launch(void* const* d_in, const int* in_sizes, int n_in,
                              void* d_out, int out_size) {
    const float* x      = (const float*)d_in[0];
    const int*   ei     = (const int*)d_in[1];
    const float* projW  = (const float*)d_in[2];
    const float* projB  = (const float*)d_in[3];
    const float* conv1W = (const float*)d_in[4];
    const float* conv1B = (const float*)d_in[5];
    const float* bn1g   = (const float*)d_in[6];
    const float* bn1b   = (const float*)d_in[7];
    const float* conv2W = (const float*)d_in[8];
    const float* conv2B = (const float*)d_in[9];
    const float* bn2g   = (const float*)d_in[10];
    const float* bn2b   = (const float*)d_in[11];
    const float* conv3W = (const float*)d_in[12];
    const float* conv3B = (const float*)d_in[13];
    const float* bn3g   = (const float*)d_in[14];
    const float* bn3b   = (const float*)d_in[15];
    const float* bypW   = (const float*)d_in[16];
    const float* bypB   = (const float*)d_in[17];
    const float* headW  = (const float*)d_in[18];
    const float* headB  = (const float*)d_in[19];
    float* out = (float*)d_out;

    int N = in_sizes[0] / 128;
    int E = in_sizes[1] / 2;
    const int* row = ei;
    const int* col = ei + E;

    float *p_h0, *p_h1, *p_byp, *p_dinv;
    __half2 *p_tmpA, *p_tmpB;
    int *p_deg, *p_rowptr, *p_cursor, *p_bsum, *p_csr;
    cudaGetSymbolAddress((void**)&p_h0, g_h0);
    cudaGetSymbolAddress((void**)&p_h1, g_h1);
    cudaGetSymbolAddress((void**)&p_tmpA, g_tmpA);
    cudaGetSymbolAddress((void**)&p_tmpB, g_tmpB);
    cudaGetSymbolAddress((void**)&p_byp, g_byp);
    cudaGetSymbolAddress((void**)&p_dinv, g_dinv);
    cudaGetSymbolAddress((void**)&p_deg, g_deg);
    cudaGetSymbolAddress((void**)&p_rowptr, g_rowptr);
    cudaGetSymbolAddress((void**)&p_cursor, g_cursor);
    cudaGetSymbolAddress((void**)&p_bsum, g_bsum);
    cudaGetSymbolAddress((void**)&p_csr, g_csr);

    int PB  = (N + 63) / 64;             // 64-row gemm tiles
    int HB  = (E + 1023) / 1024;         // hist blocks
    int SB  = (N + 1023) / 1024;         // scan1 blocks
    int SB3 = (N + 511) / 512;           // scan3 blocks
    int FB  = (N + 127) / 128;           // fused agg+gemm blocks
    int agg_blocks = (N * 32 + 255) / 256;

    // K1: proj GEMM (+bypass) interleaved with degree histogram
    merged1_kernel<<<PB + HB, 128>>>(x, projW, projB, bypW, bypB, p_h0, p_byp, N,
                                     col, p_deg, E, HB);

    // K2: scan1 (block prefixes + block sums + dinv)
    scan1_kernel<<<SB, 128>>>(p_deg, p_rowptr, p_bsum, p_dinv, N);

    // K3: conv1 GEMM -> tmpA, interleaved with scan3
    merged2_kernel<<<PB + SB3, 128>>>(p_h0, conv1W, p_dinv, p_tmpA, N,
                                      p_deg, p_rowptr, p_bsum, p_cursor,
                                      p_csr, SB, SB3);

    // K4: CSR fill (4 edges/thread MLP, + deg reset)
    fill_kernel<<<(E + 1023) / 1024, 256>>>(row, col, p_cursor, p_csr, p_deg, E, N);

    // K5: agg1 (reads tmpA) + gemm2 (writes tmpB); h1 -> gmem as layer-2 residual
    agg_gemm_kernel<<<FB, 256>>>(p_tmpA, p_csr, p_rowptr, p_dinv,
                                 conv1B, bn1g, bn1b, p_h0, p_h1,
                                 conv2W, p_tmpB, N);

    // K6: agg2 (reads tmpB) + gemm3 (writes tmpA); h2 stays in smem only
    agg_gemm_kernel<<<FB, 256>>>(p_tmpB, p_csr, p_rowptr, p_dinv,
                                 conv2B, bn2g, bn2b, p_h1, nullptr,
                                 conv3W, p_tmpA, N);

    // K7: layer-3 aggregation + head (reads tmpA)
    agg_head_kernel<<<agg_blocks, 256>>>(p_tmpA, p_csr, p_rowptr, p_dinv,
                                         conv3B, bn3g, bn3b,
                                         headW, headB, p_byp, out, N);
}

// round 15
// speedup vs baseline: 1.1743x; 1.1743x over previous
#include <cuda_runtime.h>
#include <cuda_fp16.h>
#include <cuda_bf16.h>

#define NMAX 100000
#define EMAX 1200000
#define CSRMAX (NMAX + EMAX)

// ---------------- scratch (device globals; no allocations allowed) ----------
__device__ float   g_h0[NMAX * 64];     // proj output / residual, later reused as h2
__device__ float   g_h1[NMAX * 64];     // layer1 output
__device__ __half2 g_tmp[NMAX * 32];    // dinv-scaled W-transformed features (fp16)
__device__ float   g_byp[NMAX * 3];     // bypass projection
__device__ float   g_dinv[NMAX];
__device__ int     g_deg[NMAX];         // zero at start of every execution (fill re-zeroes)
__device__ int     g_rowptr[NMAX + 1];
__device__ int     g_cursor[NMAX];
__device__ int     g_csr[CSRMAX];       // src index only (tables pre-scaled by dinv[src])
__device__ int     g_bsum[256];

// ---------------- f32x2 helpers -----------------------------------------------
__device__ __forceinline__ void ffma2(unsigned long long& d,
                                      unsigned long long a,
                                      unsigned long long b) {
    asm("fma.rn.f32x2 %0, %1, %2, %0;" : "+l"(d) : "l"(a), "l"(b));
}
__device__ __forceinline__ unsigned long long dup2(float x) {
    unsigned long long r;
    unsigned u = __float_as_uint(x);
    asm("mov.b64 %0, {%1, %1};" : "=l"(r) : "r"(u));
    return r;
}
__device__ __forceinline__ float lo32(unsigned long long v) {
    return __uint_as_float((unsigned)(v & 0xffffffffull));
}
__device__ __forceinline__ float hi32(unsigned long long v) {
    return __uint_as_float((unsigned)(v >> 32));
}

// ---------------- merged1: proj GEMM (+bypass) INTERLEAVED with hist --------
__global__ void __launch_bounds__(128) merged1_kernel(
    const float* __restrict__ x, const float* __restrict__ Wp,
    const float* __restrict__ bp, const float* __restrict__ Wb,
    const float* __restrict__ bb, float* __restrict__ h0,
    float* __restrict__ byp, int N,
    const int* __restrict__ col, int* __restrict__ deg, int E, int HB)
{
    __shared__ float Xs[64][65];
    __shared__ float Ws[64][66];
    __shared__ float Bs[3][65];
    int tid = threadIdx.x;
    int bid = blockIdx.x;

    int gemm_id;
    if (bid < 2 * HB) {
        if (bid & 1) {
            int base = (bid >> 1) * 1024;
#pragma unroll
            for (int j = 0; j < 8; ++j) {
                int e = base + j * 128 + tid;
                if (e < E) atomicAdd(&deg[col[e]], 1);
            }
            return;
        }
        gemm_id = bid >> 1;
    } else {
        gemm_id = HB + (bid - 2 * HB);
    }

    int row0 = gemm_id * 64;
    int tr  = tid >> 3;
    int tc2 = (tid & 7) * 2;

    unsigned long long acc[4][4];
    float bacc[4] = {0.f, 0.f, 0.f, 0.f};
#pragma unroll
    for (int i = 0; i < 4; ++i)
#pragma unroll
        for (int j = 0; j < 4; ++j) acc[i][j] = 0ull;

    for (int kc = 0; kc < 2; ++kc) {
        int kbase = kc * 64;
        for (int l = tid; l < 1024; l += 128) {
            int r = l >> 4, k4 = (l & 15) * 4;
            int n = row0 + r;
            float4 xv = make_float4(0.f, 0.f, 0.f, 0.f);
            if (n < N) xv = *(const float4*)(x + n * 128 + kbase + k4);
            Xs[r][k4] = xv.x; Xs[r][k4 + 1] = xv.y; Xs[r][k4 + 2] = xv.z; Xs[r][k4 + 3] = xv.w;
            float4 wv = *(const float4*)(Wp + r * 128 + kbase + k4);
            Ws[k4][r] = wv.x; Ws[k4 + 1][r] = wv.y; Ws[k4 + 2][r] = wv.z; Ws[k4 + 3][r] = wv.w;
        }
        for (int l = tid; l < 192; l += 128)
            Bs[l >> 6][l & 63] = Wb[(l >> 6) * 128 + kbase + (l & 63)];
        __syncthreads();

        int tc = tid & 7;
#pragma unroll 4
        for (int k = 0; k < 64; ++k) {
            float a_s[4];
            unsigned long long aa[4], wv[4];
#pragma unroll
            for (int i = 0; i < 4; ++i) { a_s[i] = Xs[tr + i * 16][k]; aa[i] = dup2(a_s[i]); }
#pragma unroll
            for (int j = 0; j < 4; ++j)
                wv[j] = *(const unsigned long long*)&Ws[k][tc2 + 16 * j];
#pragma unroll
            for (int i = 0; i < 4; ++i)
#pragma unroll
                for (int j = 0; j < 4; ++j) ffma2(acc[i][j], aa[i], wv[j]);
            if (tc < 3) {
                float bw = Bs[tc][k];
#pragma unroll
                for (int i = 0; i < 4; ++i) bacc[i] = fmaf(a_s[i], bw, bacc[i]);
            }
        }
        __syncthreads();
    }

    int tc = tid & 7;
#pragma unroll
    for (int i = 0; i < 4; ++i) {
        int n = row0 + tr + i * 16;
        if (n < N) {
#pragma unroll
            for (int j = 0; j < 4; ++j) {
                int c = tc2 + 16 * j;
                float2 v;
                v.x = lo32(acc[i][j]) + bp[c];
                v.y = hi32(acc[i][j]) + bp[c + 1];
                *(float2*)(h0 + n * 64 + c) = v;
            }
            if (tc < 3) byp[n * 3 + tc] = bacc[i] + bb[tc];
        }
    }
}

// ---------------- scan1: block prefix of (deg+1), block sums, AND dinv ------
__global__ void __launch_bounds__(128) scan1_kernel(
    const int* __restrict__ deg, int* __restrict__ rowptr,
    int* __restrict__ bsum, float* __restrict__ dinv, int N)
{
    __shared__ int sc[128];
    int tid = threadIdx.x;
    int sb = blockIdx.x;
    int i0 = sb * 1024 + tid * 8;
    int dl[8];
    int s = 0;
#pragma unroll
    for (int j = 0; j < 8; ++j) {
        int i = i0 + j;
        int dd = 0;
        if (i < N) {
            dd = deg[i] + 1;
            dinv[i] = rsqrtf((float)dd);
        }
        dl[j] = s;
        s += dd;
    }
    sc[tid] = s;
    __syncthreads();
    for (int off = 1; off < 128; off <<= 1) {
        int u = (tid >= off) ? sc[tid - off] : 0;
        __syncthreads();
        sc[tid] += u;
        __syncthreads();
    }
    int excl = tid ? sc[tid - 1] : 0;
#pragma unroll
    for (int j = 0; j < 8; ++j) {
        int i = i0 + j;
        if (i < N) rowptr[i] = excl + dl[j];
    }
    if (tid == 127) bsum[sb] = sc[127];
}

// ---------------- merged2: conv1 GEMM (dinv-scaled) INTERLEAVED w/ scan3 ----
__global__ void __launch_bounds__(128) merged2_kernel(
    const float* __restrict__ A, const float* __restrict__ W,
    const float* __restrict__ dinv, __half2* __restrict__ out, int N,
    const int* __restrict__ deg, int* __restrict__ rowptr,
    const int* __restrict__ bsum, int* __restrict__ cursor,
    int* __restrict__ csr, int nb, int SB3)
{
    __shared__ float Xs[64][65];
    __shared__ float Ws[64][66];
    int tid = threadIdx.x;
    int bid = blockIdx.x;

    int gemm_id;
    if (bid < 2 * SB3) {
        if (bid & 1) {
            __shared__ int sm3[128];
            int s3 = bid >> 1;
            sm3[tid] = (tid < nb) ? bsum[tid] : 0;
            __syncthreads();
            for (int off = 1; off < 128; off <<= 1) {
                int u = (tid >= off) ? sm3[tid - off] : 0;
                __syncthreads();
                sm3[tid] += u;
                __syncthreads();
            }
            int myb = s3 >> 1;
            int pref = myb ? sm3[myb - 1] : 0;
#pragma unroll
            for (int j = 0; j < 4; ++j) {
                int i = s3 * 512 + j * 128 + tid;
                if (i < N) {
                    int rp = rowptr[i] + pref;
                    rowptr[i] = rp;
                    cursor[i] = rp + 1;
                    csr[rp] = i;
                    if (i == N - 1) rowptr[N] = rp + deg[i] + 1;
                }
            }
            return;
        }
        gemm_id = bid >> 1;
    } else {
        gemm_id = SB3 + (bid - 2 * SB3);
    }

    int row0 = gemm_id * 64;
    int tr  = tid >> 3;
    int tc2 = (tid & 7) * 2;

    for (int l = tid; l < 1024; l += 128) {
        int r = l >> 4, k4 = (l & 15) * 4;
        int n = row0 + r;
        float4 xv = make_float4(0.f, 0.f, 0.f, 0.f);
        if (n < N) xv = *(const float4*)(A + n * 64 + k4);
        Xs[r][k4] = xv.x; Xs[r][k4 + 1] = xv.y; Xs[r][k4 + 2] = xv.z; Xs[r][k4 + 3] = xv.w;
        float4 wv = *(const float4*)(W + r * 64 + k4);
        Ws[k4][r] = wv.x; Ws[k4 + 1][r] = wv.y; Ws[k4 + 2][r] = wv.z; Ws[k4 + 3][r] = wv.w;
    }
    __syncthreads();

    unsigned long long acc[4][4];
#pragma unroll
    for (int i = 0; i < 4; ++i)
#pragma unroll
        for (int j = 0; j < 4; ++j) acc[i][j] = 0ull;

#pragma unroll 4
    for (int k = 0; k < 64; ++k) {
        unsigned long long aa[4], wv[4];
#pragma unroll
        for (int i = 0; i < 4; ++i) aa[i] = dup2(Xs[tr + i * 16][k]);
#pragma unroll
        for (int j = 0; j < 4; ++j)
            wv[j] = *(const unsigned long long*)&Ws[k][tc2 + 16 * j];
#pragma unroll
        for (int i = 0; i < 4; ++i)
#pragma unroll
            for (int j = 0; j < 4; ++j) ffma2(acc[i][j], aa[i], wv[j]);
    }

#pragma unroll
    for (int i = 0; i < 4; ++i) {
        int n = row0 + tr + i * 16;
        if (n < N) {
            float dvn = dinv[n];
#pragma unroll
            for (int j = 0; j < 4; ++j) {
                float2 v = make_float2(lo32(acc[i][j]) * dvn, hi32(acc[i][j]) * dvn);
                out[n * 32 + (tc2 >> 1) + 8 * j] = __float22half2_rn(v);
            }
        }
    }
}

// ---------------- fill: 4-byte CSR scatter (+ deg reset), 1 edge/thread -----
__global__ void fill_kernel(const int* __restrict__ row, const int* __restrict__ col,
                            int* __restrict__ cursor, int* __restrict__ csr,
                            int* __restrict__ deg, int E, int N) {
    int e = blockIdx.x * blockDim.x + threadIdx.x;
    if (e < N) deg[e] = 0;               // reset for next execution
    if (e >= E) return;
    int d = col[e];
    int pos = atomicAdd(&cursor[d], 1);
    csr[pos] = row[e];
}

// ---------------- aggregation (warp per node, half-warp per edge stream) ----
// Tables pre-scaled by dinv[src]; csr = src index only. 4 edges/half/iter.
__global__ void __launch_bounds__(256) agg_kernel(
    const __half2* __restrict__ tmp, const int* __restrict__ csr,
    const int* __restrict__ rowptr, const float* __restrict__ dinv,
    const float* __restrict__ convb, const float* __restrict__ bng,
    const float* __restrict__ bnb, const float* __restrict__ resid,
    float* __restrict__ outh, const float* __restrict__ headW,
    const float* __restrict__ headb, const float* __restrict__ byp,
    float* __restrict__ out, int N, int mode)
{
    int gt = blockIdx.x * blockDim.x + threadIdx.x;
    int v = gt >> 5;
    int lane = gt & 31;
    if (v >= N) return;
    int half = lane >> 4;
    int sub  = lane & 15;

    const uint2* hp = (const uint2*)tmp;
    int s = rowptr[v];
    int e = rowptr[v + 1];

    float a0 = 0.f, a1 = 0.f, a2 = 0.f, a3 = 0.f;
    int p = s + half;
    for (; p + 6 < e; p += 8) {
        int s0 = csr[p];
        int s1 = csr[p + 2];
        int s2 = csr[p + 4];
        int s3 = csr[p + 6];
        uint2 r0 = hp[s0 * 16 + sub];
        uint2 r1 = hp[s1 * 16 + sub];
        uint2 r2 = hp[s2 * 16 + sub];
        uint2 r3 = hp[s3 * 16 + sub];
        float2 f00 = __half22float2(*(__half2*)&r0.x);
        float2 f01 = __half22float2(*(__half2*)&r0.y);
        float2 f10 = __half22float2(*(__half2*)&r1.x);
        float2 f11 = __half22float2(*(__half2*)&r1.y);
        float2 f20 = __half22float2(*(__half2*)&r2.x);
        float2 f21 = __half22float2(*(__half2*)&r2.y);
        float2 f30 = __half22float2(*(__half2*)&r3.x);
        float2 f31 = __half22float2(*(__half2*)&r3.y);
        a0 += (f00.x + f10.x) + (f20.x + f30.x);
        a1 += (f00.y + f10.y) + (f20.y + f30.y);
        a2 += (f01.x + f11.x) + (f21.x + f31.x);
        a3 += (f01.y + f11.y) + (f21.y + f31.y);
    }
    for (; p < e; p += 2) {
        int s0 = csr[p];
        uint2 r0 = hp[s0 * 16 + sub];
        float2 f00 = __half22float2(*(__half2*)&r0.x);
        float2 f01 = __half22float2(*(__half2*)&r0.y);
        a0 += f00.x;
        a1 += f00.y;
        a2 += f01.x;
        a3 += f01.y;
    }
    a0 += __shfl_xor_sync(0xffffffffu, a0, 16);
    a1 += __shfl_xor_sync(0xffffffffu, a1, 16);
    a2 += __shfl_xor_sync(0xffffffffu, a2, 16);
    a3 += __shfl_xor_sync(0xffffffffu, a3, 16);

    float dv = dinv[v];
    const float bninv = rsqrtf(1.0f + 1e-5f);

    if (mode == 0) {
        if (half == 0) {
            int c = sub * 4;
            float4 cb = *(const float4*)(convb + c);
            float4 bg = *(const float4*)(bng + c);
            float4 bo = *(const float4*)(bnb + c);
            float4 r  = *(const float4*)(resid + v * 64 + c);
            float4 o;
            o.x = fmaxf(fmaf(fmaf(a0, dv, cb.x), bg.x * bninv, bo.x), 0.f) + r.x;
            o.y = fmaxf(fmaf(fmaf(a1, dv, cb.y), bg.y * bninv, bo.y), 0.f) + r.y;
            o.z = fmaxf(fmaf(fmaf(a2, dv, cb.z), bg.z * bninv, bo.z), 0.f) + r.z;
            o.w = fmaxf(fmaf(fmaf(a3, dv, cb.w), bg.w * bninv, bo.w), 0.f) + r.w;
            *(float4*)(outh + v * 64 + c) = o;
        }
    } else {
        float p0 = 0.f, p1 = 0.f, p2 = 0.f;
        if (half == 0) {
            int c = sub * 4;
            float4 cb = *(const float4*)(convb + c);
            float4 bg = *(const float4*)(bng + c);
            float4 bo = *(const float4*)(bnb + c);
            float v0 = fmaxf(fmaf(fmaf(a0, dv, cb.x), bg.x * bninv, bo.x), 0.f);
            float v1 = fmaxf(fmaf(fmaf(a1, dv, cb.y), bg.y * bninv, bo.y), 0.f);
            float v2 = fmaxf(fmaf(fmaf(a2, dv, cb.z), bg.z * bninv, bo.z), 0.f);
            float v3 = fmaxf(fmaf(fmaf(a3, dv, cb.w), bg.w * bninv, bo.w), 0.f);
            p0 = v0 * headW[c]       + v1 * headW[c + 1]       + v2 * headW[c + 2]       + v3 * headW[c + 3];
            p1 = v0 * headW[67 + c]  + v1 * headW[67 + c + 1]  + v2 * headW[67 + c + 2]  + v3 * headW[67 + c + 3];
            p2 = v0 * headW[134 + c] + v1 * headW[134 + c + 1] + v2 * headW[134 + c + 2] + v3 * headW[134 + c + 3];
        }
#pragma unroll
        for (int o = 8; o > 0; o >>= 1) {
            p0 += __shfl_xor_sync(0xffffffffu, p0, o);
            p1 += __shfl_xor_sync(0xffffffffu, p1, o);
            p2 += __shfl_xor_sync(0xffffffffu, p2, o);
        }
        if (lane == 0) {
            float b0 = byp[v * 3], b1 = byp[v * 3 + 1], b2 = byp[v * 3 + 2];
            p0 += headW[64] * b0 + headW[65] * b1 + headW[66] * b2 + headb[0];
            p1 += headW[67 + 64] * b0 + headW[67 + 65] * b1 + headW[67 + 66] * b2 + headb[1];
            p2 += headW[134 + 64] * b0 + headW[134 + 65] * b1 + headW[134 + 66] * b2 + headb[2];
            float kappa = fminf(fmaxf(p0 * 5.f + 2.5f, 0.2f), 10.f);
            float tau   = fminf(fmaxf(p2 + 0.5f, 0.05f), 2.f);
            out[v * 3]     = kappa;
            out[v * 3 + 1] = p1;
            out[v * 3 + 2] = tau;
        }
    }
}

// ---------------- launch -----------------------------------------------------
extern "C" void kernel_launch(void* const* d_in, const int* in_sizes, int n_in,
                              void* d_out, int out_size) {
    const float* x      = (const float*)d_in[0];
    const int*   ei     = (const int*)d_in[1];
    const float* projW  = (const float*)d_in[2];
    const float* projB  = (const float*)d_in[3];
    const float* conv1W = (const float*)d_in[4];
    const float* conv1B = (const float*)d_in[5];
    const float* bn1g   = (const float*)d_in[6];
    const float* bn1b   = (const float*)d_in[7];
    const float* conv2W = (const float*)d_in[8];
    const float* conv2B = (const float*)d_in[9];
    const float* bn2g   = (const float*)d_in[10];
    const float* bn2b   = (const float*)d_in[11];
    const float* conv3W = (const float*)d_in[12];
    const float* conv3B = (const float*)d_in[13];
    const float* bn3g   = (const float*)d_in[14];
    const float* bn3b   = (const float*)d_in[15];
    const float* bypW   = (const float*)d_in[16];
    const float* bypB   = (const float*)d_in[17];
    const float* headW  = (const float*)d_in[18];
    const float* headB  = (const float*)d_in[19];
    float* out = (float*)d_out;

    int N = in_sizes[0] / 128;
    int E = in_sizes[1] / 2;
    const int* row = ei;
    const int* col = ei + E;

    float *p_h0, *p_h1, *p_byp, *p_dinv;
    __half2* p_tmp;
    int *p_deg, *p_rowptr, *p_cursor, *p_bsum, *p_csr;
    cudaGetSymbolAddress((void**)&p_h0, g_h0);
    cudaGetSymbolAddress((void**)&p_h1, g_h1);
    cudaGetSymbolAddress((void**)&p_tmp, g_tmp);
    cudaGetSymbolAddress((void**)&p_byp, g_byp);
    cudaGetSymbolAddress((void**)&p_dinv, g_dinv);
    cudaGetSymbolAddress((void**)&p_deg, g_deg);
    cudaGetSymbolAddress((void**)&p_rowptr, g_rowptr);
    cudaGetSymbolAddress((void**)&p_cursor, g_cursor);
    cudaGetSymbolAddress((void**)&p_bsum, g_bsum);
    cudaGetSymbolAddress((void**)&p_csr, g_csr);

    int PB  = (N + 63) / 64;             // gemm tiles
    int HB  = (E + 1023) / 1024;         // hist blocks (1024 edges each)
    int SB  = (N + 1023) / 1024;         // scan1 blocks
    int SB3 = (N + 511) / 512;           // scan3 blocks (512 nodes each)
    int agg_blocks = (N * 32 + 255) / 256;

    // K1: proj GEMM (+bypass) interleaved with degree histogram
    merged1_kernel<<<PB + HB, 128>>>(x, projW, projB, bypW, bypB, p_h0, p_byp, N,
                                     col, p_deg, E, HB);

    // K2: scan1 (block prefixes + block sums + dinv)
    scan1_kernel<<<SB, 128>>>(p_deg, p_rowptr, p_bsum, p_dinv, N);

    // K3: conv1 GEMM (dinv-scaled fp16 table) interleaved with scan3
    merged2_kernel<<<PB + SB3, 128>>>(p_h0, conv1W, p_dinv, p_tmp, N,
                                      p_deg, p_rowptr, p_bsum, p_cursor,
                                      p_csr, SB, SB3);

    // K4: CSR fill (+ deg reset)
    fill_kernel<<<(E + 255) / 256, 256>>>(row, col, p_cursor, p_csr, p_deg, E, N);

    // K5: layer-1 aggregation
    agg_kernel<<<agg_blocks, 256>>>(p_tmp, p_csr, p_rowptr, p_dinv,
                                    conv1B, bn1g, bn1b, p_h0, p_h1,
                                    nullptr, nullptr, nullptr, nullptr, N, 0);

    // K6/K7: layer 2
    gemm64h_launch:
    merged2_kernel<<<PB, 128>>>(p_h1, conv2W, p_dinv, p_tmp, N,
                                p_deg, p_rowptr, p_bsum, p_cursor,
                                p_csr, SB, 0);
    agg_kernel<<<agg_blocks, 256>>>(p_tmp, p_csr, p_rowptr, p_dinv,
                                    conv2B, bn2g, bn2b, p_h1, p_h0,
                                    nullptr, nullptr, nullptr, nullptr, N, 0);

    // K8/K9: layer 3 + head fused
    merged2_kernel<<<PB, 128>>>(p_h0, conv3W, p_dinv, p_tmp, N,
                                p_deg, p_rowptr, p_bsum, p_cursor,
                                p_csr, SB, 0);
    agg_kernel<<<agg_blocks, 256>>>(p_tmp, p_csr, p_rowptr, p_dinv,
                                    conv3B, bn3g, bn3b, nullptr, nullptr,
                                    headW, headB, p_byp, out, N, 1);
}